// round 6
// baseline (speedup 1.0000x reference)
#include <cuda_runtime.h>
#include <cuda_bf16.h>
#include <math.h>
#include <stdint.h>

#define BATCH 2
#define LSEQ  1024
#define DM    1024
#define DI    2048
#define NST   16
#define RK    64
#define DBC_W (RK + 2*NST)   /* 96 */
#define NL    4
#define MROWS (BATCH*LSEQ)   /* 2048 */
#define KSPLIT 8

typedef __nv_bfloat16 bf16;

// ---------------- fp32 scratch ----------------------------------------------
__device__ float g_x    [MROWS*DM];
__device__ float g_xz   [MROWS*2*DI];
__device__ float g_xc   [MROWS*DI];
__device__ float g_dbc  [MROWS*DBC_W];
__device__ float g_part [KSPLIT*MROWS*DBC_W];
__device__ float g_delta[MROWS*DI];

// ---------------- bf16 scratch (GEMM inputs) --------------------------------
__device__ bf16 g_h_bf  [MROWS*DM];
__device__ bf16 g_xc_bf [MROWS*DI];
__device__ bf16 g_dbc_bf[MROWS*DBC_W];
__device__ bf16 g_u_bf  [MROWS*DI];
__device__ bf16 g_Win_bf [NL*2*DI*DM];
__device__ bf16 g_Wx_bf  [NL*DBC_W*DI];
__device__ bf16 g_Wdt_bf [NL*DI*RK];
__device__ bf16 g_Wout_bf[NL*DM*DI];

// ---------------- helpers ---------------------------------------------------
__device__ __forceinline__ float siluf(float v) { return v / (1.f + __expf(-v)); }
__device__ __forceinline__ float softplusf(float v) {
    return (v > 20.f) ? v : log1pf(__expf(v));
}
__device__ __forceinline__ void cp16(uint32_t s, const void* g, bool pred) {
    if (pred)
        asm volatile("cp.async.cg.shared.global [%0], [%1], 16;" :: "r"(s), "l"(g));
    else
        asm volatile("cp.async.cg.shared.global [%0], [%1], 16, 0;" :: "r"(s), "l"(g));
}

// ---------------- fp32 -> bf16 bulk convert (vectorized) --------------------
__global__ void f2bf_k(const float4* __restrict__ s, __nv_bfloat162* __restrict__ d, int n4) {
    int i = blockIdx.x * blockDim.x + threadIdx.x;
    for (; i < n4; i += gridDim.x * blockDim.x) {
        float4 v = s[i];
        d[2*i]   = __floats2bfloat162_rn(v.x, v.y);
        d[2*i+1] = __floats2bfloat162_rn(v.z, v.w);
    }
}

// ---------------- copy input residual ---------------------------------------
__global__ void copy_in_k(const float4* __restrict__ x) {
    int i = blockIdx.x * blockDim.x + threadIdx.x;
    if (i < MROWS*DM/4) ((float4*)g_x)[i] = x[i];
}

// ---------------- RMSNorm (writes bf16 h) ------------------------------------
__global__ void rmsnorm_k(const float* __restrict__ w) {
    int row = blockIdx.x;
    const float* xr = g_x + row * DM;
    __shared__ float red[256];
    float s = 0.f;
    for (int i = threadIdx.x; i < DM; i += 256) { float v = xr[i]; s += v * v; }
    red[threadIdx.x] = s;
    __syncthreads();
    for (int off = 128; off > 0; off >>= 1) {
        if (threadIdx.x < off) red[threadIdx.x] += red[threadIdx.x + off];
        __syncthreads();
    }
    float inv = rsqrtf(red[0] * (1.f / DM) + 1e-5f);
    bf16* hr = g_h_bf + (size_t)row * DM;
    for (int i = threadIdx.x; i < DM; i += 256)
        hr[i] = __float2bfloat16(xr[i] * inv * w[i]);
}

// ---------------- bf16 tensor-core NT GEMM ----------------------------------
// 3-stage cp.async pipeline + register double-buffered ldmatrix fragments.
// C[m,n] = sum_k A[m,k]*B[n,k] (+epilogue). A,B bf16; C fp32.
// Block tile 128x128x64, 8 warps (warp 64x32), mma.m16n8k16 bf16.
// smem: 3 stages x (A 16KB | B 16KB) = 96KB. 128B rows, 16B-chunk XOR swizzle.
#define STAGEB 32768u
#define NSTAGE 3
#define GSMEM  (NSTAGE * STAGEB)

__global__ __launch_bounds__(256) void bf16gemm_nt_k(
    const bf16* __restrict__ A, int lda,
    const bf16* __restrict__ B, int ldb,
    float* __restrict__ C, int ldc,
    const float* __restrict__ bias,
    const float* __restrict__ resid,
    int M, int N, int K, int epi,
    int kspan, size_t cspan)
{
    extern __shared__ char smem[];
    A += (size_t)blockIdx.z * kspan;
    B += (size_t)blockIdx.z * kspan;
    C += (size_t)blockIdx.z * cspan;

    const int tid  = threadIdx.x;
    const int warp = tid >> 5;
    const int lane = tid & 31;
    const int m0 = blockIdx.y * 128;
    const int n0 = blockIdx.x * 128;
    const int wm = (warp >> 2) * 64;
    const int wn = (warp & 3) * 32;

    float c[4][4][4];
#pragma unroll
    for (int i = 0; i < 4; i++)
#pragma unroll
        for (int j = 0; j < 4; j++)
#pragma unroll
            for (int r = 0; r < 4; r++) c[i][j][r] = 0.f;

    const uint32_t sbase = (uint32_t)__cvta_generic_to_shared(smem);
    const int nk = K >> 6;

    const int lane8 = lane & 7;
    const int lmat  = lane >> 3;
    // per-thread cp.async coords (fixed)
    const int cpr = tid >> 1;            // row 0..127
    const int cpc = (tid & 1) << 2;      // chunk 0 or 4 (two 16B chunks each? no:)
    // each thread copies 4 chunks: rows cpr, chunks cpc..cpc+3
    // (128 rows x 8 chunks = 1024 chunks; 256 thr x 4 = 1024)

    // ---- prologue: issue stages 0..NSTAGE-2 plus keep group count uniform ----
#pragma unroll
    for (int t = 0; t < NSTAGE - 1; t++) {
        if (t < nk) {
            uint32_t st = sbase + (uint32_t)t * STAGEB;
            const int k0 = t << 6;
#pragma unroll
            for (int i = 0; i < 4; i++) {
                int cc = cpc + i;
                uint32_t so = (uint32_t)((cpr << 7) + ((cc ^ (cpr & 7)) << 4));
                cp16(st + so,           A + (size_t)(m0 + cpr) * lda + k0 + cc * 8, (m0 + cpr) < M);
                cp16(st + 16384u + so,  B + (size_t)(n0 + cpr) * ldb + k0 + cc * 8, (n0 + cpr) < N);
            }
        }
        asm volatile("cp.async.commit_group;" ::: "memory");
    }

    for (int kt = 0; kt < nk; kt++) {
        // stage kt%NSTAGE is complete once <= NSTAGE-2 groups pending
        asm volatile("cp.async.wait_group %0;" :: "n"(NSTAGE - 2) : "memory");
        __syncthreads();

        // ---- issue refill for k-tile kt+NSTAGE-1 into stage (kt+NSTAGE-1)%NSTAGE
        // (that stage's last readers finished at iter kt-1; the sync above covers it)
        if (kt + NSTAGE - 1 < nk) {
            const int k0 = (kt + NSTAGE - 1) << 6;
            uint32_t st = sbase + (uint32_t)((kt + NSTAGE - 1) % NSTAGE) * STAGEB;
#pragma unroll
            for (int i = 0; i < 4; i++) {
                int cc = cpc + i;
                uint32_t so = (uint32_t)((cpr << 7) + ((cc ^ (cpr & 7)) << 4));
                cp16(st + so,          A + (size_t)(m0 + cpr) * lda + k0 + cc * 8, (m0 + cpr) < M);
                cp16(st + 16384u + so, B + (size_t)(n0 + cpr) * ldb + k0 + cc * 8, (n0 + cpr) < N);
            }
        }
        asm volatile("cp.async.commit_group;" ::: "memory");

        // ---- compute on stage kt%NSTAGE with fragment double buffering ----
        const uint32_t sA = sbase + (uint32_t)(kt % NSTAGE) * STAGEB;
        const uint32_t sB = sA + 16384u;

        uint32_t af[2][4][4];
        uint32_t bfr[2][4][2];

        // load fragments for ks = 0 into buffer 0
        {
            const int ks = 0;
#pragma unroll
            for (int mt = 0; mt < 4; mt++) {
                int ar = wm + mt * 16 + ((lmat & 1) << 3) + lane8;
                int ac = (ks << 1) + (lmat >> 1);
                uint32_t addr = sA + (uint32_t)((ar << 7) + ((ac ^ (ar & 7)) << 4));
                asm volatile("ldmatrix.sync.aligned.m8n8.x4.shared.b16 {%0,%1,%2,%3}, [%4];"
                             : "=r"(af[0][mt][0]), "=r"(af[0][mt][1]),
                               "=r"(af[0][mt][2]), "=r"(af[0][mt][3]) : "r"(addr));
            }
#pragma unroll
            for (int np = 0; np < 2; np++) {
                int br = wn + np * 16 + ((lmat >> 1) << 3) + lane8;
                int bc = (ks << 1) + (lmat & 1);
                uint32_t addr = sB + (uint32_t)((br << 7) + ((bc ^ (br & 7)) << 4));
                asm volatile("ldmatrix.sync.aligned.m8n8.x4.shared.b16 {%0,%1,%2,%3}, [%4];"
                             : "=r"(bfr[0][np*2][0]), "=r"(bfr[0][np*2][1]),
                               "=r"(bfr[0][np*2+1][0]), "=r"(bfr[0][np*2+1][1]) : "r"(addr));
            }
        }

#pragma unroll
        for (int ks = 0; ks < 4; ks++) {
            const int cur = ks & 1;
            const int nxt = cur ^ 1;
            if (ks < 3) {
                const int k2 = ks + 1;
#pragma unroll
                for (int mt = 0; mt < 4; mt++) {
                    int ar = wm + mt * 16 + ((lmat & 1) << 3) + lane8;
                    int ac = (k2 << 1) + (lmat >> 1);
                    uint32_t addr = sA + (uint32_t)((ar << 7) + ((ac ^ (ar & 7)) << 4));
                    asm volatile("ldmatrix.sync.aligned.m8n8.x4.shared.b16 {%0,%1,%2,%3}, [%4];"
                                 : "=r"(af[nxt][mt][0]), "=r"(af[nxt][mt][1]),
                                   "=r"(af[nxt][mt][2]), "=r"(af[nxt][mt][3]) : "r"(addr));
                }
#pragma unroll
                for (int np = 0; np < 2; np++) {
                    int br = wn + np * 16 + ((lmat >> 1) << 3) + lane8;
                    int bc = (k2 << 1) + (lmat & 1);
                    uint32_t addr = sB + (uint32_t)((br << 7) + ((bc ^ (br & 7)) << 4));
                    asm volatile("ldmatrix.sync.aligned.m8n8.x4.shared.b16 {%0,%1,%2,%3}, [%4];"
                                 : "=r"(bfr[nxt][np*2][0]), "=r"(bfr[nxt][np*2][1]),
                                   "=r"(bfr[nxt][np*2+1][0]), "=r"(bfr[nxt][np*2+1][1]) : "r"(addr));
                }
            }
#pragma unroll
            for (int mt = 0; mt < 4; mt++)
#pragma unroll
                for (int nt = 0; nt < 4; nt++) {
                    asm volatile(
                        "mma.sync.aligned.m16n8k16.row.col.f32.bf16.bf16.f32 "
                        "{%0,%1,%2,%3}, {%4,%5,%6,%7}, {%8,%9}, {%0,%1,%2,%3};"
                        : "+f"(c[mt][nt][0]), "+f"(c[mt][nt][1]),
                          "+f"(c[mt][nt][2]), "+f"(c[mt][nt][3])
                        : "r"(af[cur][mt][0]), "r"(af[cur][mt][1]),
                          "r"(af[cur][mt][2]), "r"(af[cur][mt][3]),
                          "r"(bfr[cur][nt][0]), "r"(bfr[cur][nt][1]));
                }
        }
    }

    // ---- epilogue (float2 stores) ----
#pragma unroll
    for (int mt = 0; mt < 4; mt++) {
#pragma unroll
        for (int nt = 0; nt < 4; nt++) {
            int m = m0 + wm + mt * 16 + (lane >> 2);
            int n = n0 + wn + nt * 8 + 2 * (lane & 3);
#pragma unroll
            for (int half = 0; half < 2; half++) {
                int mm = m + half * 8;
                if (mm >= M || n >= N) continue;
                float v0 = c[mt][nt][half * 2];
                float v1 = c[mt][nt][half * 2 + 1];
                if (epi == 1) {
                    v0 = softplusf(v0 + bias[n]);
                    v1 = softplusf(v1 + bias[n + 1]);
                } else if (epi == 2) {
                    const float2 rv = *(const float2*)(resid + (size_t)mm * ldc + n);
                    v0 += rv.x; v1 += rv.y;
                }
                *(float2*)(C + (size_t)mm * ldc + n) = make_float2(v0, v1);
            }
        }
    }
}

// ---------------- split-K reduction (fp32 + bf16 out) ------------------------
__global__ void reduce_part_k() {
    int i = blockIdx.x * blockDim.x + threadIdx.x;
    if (i >= MROWS * DBC_W) return;
    float s = 0.f;
#pragma unroll
    for (int p = 0; p < KSPLIT; p++) s += g_part[(size_t)p * MROWS * DBC_W + i];
    g_dbc[i] = s;
    g_dbc_bf[i] = __float2bfloat16(s);
}

// ---------------- causal depthwise conv1d (k=4) + SiLU ----------------------
__global__ void conv_silu_k(const float* __restrict__ cw, const float* __restrict__ cb) {
    int idx = blockIdx.x * blockDim.x + threadIdx.x;
    if (idx >= MROWS * DI) return;
    int d = idx % DI;
    int l = (idx / DI) % LSEQ;
    int b = idx / (DI * LSEQ);
    float acc = cb[d];
#pragma unroll
    for (int k = 0; k < 4; k++) {
        int ls = l - 3 + k;
        if (ls >= 0)
            acc = fmaf(g_xz[((size_t)(b * LSEQ + ls)) * (2 * DI) + d], cw[d * 4 + k], acc);
    }
    float v = siluf(acc);
    g_xc[idx] = v;
    g_xc_bf[idx] = __float2bfloat16(v);
}

// ---------------- selective scan (pipelined), writes bf16 u -----------------
__global__ void scan_k(const float* __restrict__ A_log, const float* __restrict__ Dw) {
    int t = blockIdx.x * blockDim.x + threadIdx.x;
    int n = t & 15;
    int p = t >> 4;
    if (p >= BATCH * DI) return;
    int d = p % DI;
    int b = p / DI;

    float A  = -__expf(A_log[d * NST + n]);
    float Dd = Dw[d];
    float h  = 0.f;

    size_t rowD  = (size_t)(b * LSEQ) * DI + d;
    size_t row96 = (size_t)(b * LSEQ) * DBC_W;
    size_t rowZ  = (size_t)(b * LSEQ) * (2 * DI) + DI + d;

    float dt = g_delta[rowD];
    float xv = g_xc[rowD];
    float Bn = g_dbc[row96 + RK + n];
    float Cn = g_dbc[row96 + RK + NST + n];
    float zv = g_xz[rowZ];

#pragma unroll 2
    for (int l = 0; l < LSEQ; l++) {
        size_t rowD1  = rowD + DI;
        size_t row961 = row96 + DBC_W;
        size_t rowZ1  = rowZ + 2 * DI;
        float dt1 = 0.f, xv1 = 0.f, Bn1 = 0.f, Cn1 = 0.f, zv1 = 0.f;
        if (l + 1 < LSEQ) {
            dt1 = g_delta[rowD1];
            xv1 = g_xc[rowD1];
            Bn1 = g_dbc[row961 + RK + n];
            Cn1 = g_dbc[row961 + RK + NST + n];
            zv1 = g_xz[rowZ1];
        }

        h = fmaf(__expf(dt * A), h, dt * xv * Bn);

        float y = h * Cn;
        y += __shfl_xor_sync(0xffffffffu, y, 8);
        y += __shfl_xor_sync(0xffffffffu, y, 4);
        y += __shfl_xor_sync(0xffffffffu, y, 2);
        y += __shfl_xor_sync(0xffffffffu, y, 1);

        if (n == 0)
            g_u_bf[rowD] = __float2bfloat16((y + Dd * xv) * siluf(zv));

        dt = dt1; xv = xv1; Bn = Bn1; Cn = Cn1; zv = zv1;
        rowD = rowD1; row96 = row961; rowZ = rowZ1;
    }
}

// ---------------- host orchestration ----------------------------------------
extern "C" void kernel_launch(void* const* d_in, const int* in_sizes, int n_in,
                              void* d_out, int out_size) {
    const float* x      = (const float*)d_in[0];
    const float* norm_w = (const float*)d_in[1];
    const float* W_in   = (const float*)d_in[2];
    const float* conv_w = (const float*)d_in[3];
    const float* conv_b = (const float*)d_in[4];
    const float* W_x    = (const float*)d_in[5];
    const float* W_dt   = (const float*)d_in[6];
    const float* b_dt   = (const float*)d_in[7];
    const float* A_log  = (const float*)d_in[8];
    const float* Dpar   = (const float*)d_in[9];
    const float* W_out  = (const float*)d_in[10];
    float* out = (float*)d_out;

    float *px, *pxz, *ppart, *pdelta;
    bf16 *ph_bf, *pxc_bf, *pdbc_bf, *pu_bf, *pWin, *pWx, *pWdt, *pWout;
    cudaGetSymbolAddress((void**)&px,     g_x);
    cudaGetSymbolAddress((void**)&pxz,    g_xz);
    cudaGetSymbolAddress((void**)&ppart,  g_part);
    cudaGetSymbolAddress((void**)&pdelta, g_delta);
    cudaGetSymbolAddress((void**)&ph_bf,  g_h_bf);
    cudaGetSymbolAddress((void**)&pxc_bf, g_xc_bf);
    cudaGetSymbolAddress((void**)&pdbc_bf,g_dbc_bf);
    cudaGetSymbolAddress((void**)&pu_bf,  g_u_bf);
    cudaGetSymbolAddress((void**)&pWin,   g_Win_bf);
    cudaGetSymbolAddress((void**)&pWx,    g_Wx_bf);
    cudaGetSymbolAddress((void**)&pWdt,   g_Wdt_bf);
    cudaGetSymbolAddress((void**)&pWout,  g_Wout_bf);

    const int M = MROWS;
    cudaFuncSetAttribute(bf16gemm_nt_k,
                         cudaFuncAttributeMaxDynamicSharedMemorySize, GSMEM);

    dim3 thr(256);
    copy_in_k<<<(MROWS*DM/4 + 255) / 256, 256>>>((const float4*)x);

    // weights -> bf16 (once per launch)
    f2bf_k<<<1184, 256>>>((const float4*)W_in,  (__nv_bfloat162*)pWin,  NL * 2 * DI * DM / 4);
    f2bf_k<<<296,  256>>>((const float4*)W_x,   (__nv_bfloat162*)pWx,   NL * DBC_W * DI / 4);
    f2bf_k<<<296,  256>>>((const float4*)W_dt,  (__nv_bfloat162*)pWdt,  NL * DI * RK / 4);
    f2bf_k<<<1184, 256>>>((const float4*)W_out, (__nv_bfloat162*)pWout, NL * DM * DI / 4);

    for (int l = 0; l < NL; l++) {
        rmsnorm_k<<<M, 256>>>(norm_w + (size_t)l * DM);

        // 2) xz = h @ W_in^T   [M, 2*DI]
        {
            dim3 g(2 * DI / 128, M / 128, 1);
            bf16gemm_nt_k<<<g, thr, GSMEM>>>(ph_bf, DM, pWin + (size_t)l * 2 * DI * DM, DM,
                                             pxz, 2 * DI, nullptr, nullptr,
                                             M, 2 * DI, DM, 0, 0, 0);
        }

        conv_silu_k<<<(MROWS*DI + 255) / 256, 256>>>(
            conv_w + (size_t)l * DI * 4, conv_b + (size_t)l * DI);

        // 4) dbc = xc @ W_x^T   [M, 96]  split-K=8 + reduce
        {
            const int Kc = DI / KSPLIT;  // 256
            dim3 g(1, M / 128, KSPLIT);
            bf16gemm_nt_k<<<g, thr, GSMEM>>>(pxc_bf, DI, pWx + (size_t)l * DBC_W * DI, DI,
                                             ppart, DBC_W, nullptr, nullptr,
                                             M, DBC_W, Kc, 0,
                                             Kc, (size_t)M * DBC_W);
            reduce_part_k<<<(MROWS * DBC_W + 255) / 256, 256>>>();
        }

        // 5) delta = softplus(dbc[:, :64] @ W_dt^T + b_dt)   [M, DI]
        {
            dim3 g(DI / 128, M / 128, 1);
            bf16gemm_nt_k<<<g, thr, GSMEM>>>(pdbc_bf, DBC_W, pWdt + (size_t)l * DI * RK, RK,
                                             pdelta, DI, b_dt + (size_t)l * DI, nullptr,
                                             M, DI, RK, 1, 0, 0);
        }

        scan_k<<<(BATCH * DI * NST) / 256, 256>>>(
            A_log + (size_t)l * DI * NST, Dpar + (size_t)l * DI);

        // 7) x = x + u @ W_out^T   [M, DM]
        {
            float* Cout = (l == NL - 1) ? out : px;
            dim3 g(DM / 128, M / 128, 1);
            bf16gemm_nt_k<<<g, thr, GSMEM>>>(pu_bf, DI, pWout + (size_t)l * DM * DI, DI,
                                             Cout, DM, nullptr, px,
                                             M, DM, DI, 2, 0, 0);
        }
    }
}

// round 7
// speedup vs baseline: 1.0043x; 1.0043x over previous
#include <cuda_runtime.h>
#include <cuda_bf16.h>
#include <math.h>
#include <stdint.h>

#define BATCH 2
#define LSEQ  1024
#define DM    1024
#define DI    2048
#define NST   16
#define RK    64
#define DBC_W (RK + 2*NST)   /* 96 */
#define NL    4
#define MROWS (BATCH*LSEQ)   /* 2048 */
#define KSPLIT 8

typedef __nv_bfloat16 bf16;

// ---------------- fp32 scratch ----------------------------------------------
__device__ float g_x    [MROWS*DM];
__device__ float g_xz   [MROWS*2*DI];
__device__ float g_xc   [MROWS*DI];
__device__ float g_dbc  [MROWS*DBC_W];
__device__ float g_part [KSPLIT*MROWS*DBC_W];
__device__ float g_delta[MROWS*DI];

// ---------------- bf16 scratch (GEMM inputs) --------------------------------
__device__ bf16 g_h_bf  [MROWS*DM];
__device__ bf16 g_xc_bf [MROWS*DI];
__device__ bf16 g_dbc_bf[MROWS*DBC_W];
__device__ bf16 g_u_bf  [MROWS*DI];
__device__ bf16 g_Win_bf [NL*2*DI*DM];
__device__ bf16 g_Wx_bf  [NL*DBC_W*DI];
__device__ bf16 g_Wdt_bf [NL*DI*RK];
__device__ bf16 g_Wout_bf[NL*DM*DI];

// ---------------- helpers ---------------------------------------------------
__device__ __forceinline__ float siluf(float v) { return v / (1.f + __expf(-v)); }
__device__ __forceinline__ float softplusf(float v) {
    return (v > 20.f) ? v : log1pf(__expf(v));
}
__device__ __forceinline__ void cp16(uint32_t s, const void* g, bool pred) {
    if (pred)
        asm volatile("cp.async.cg.shared.global [%0], [%1], 16;" :: "r"(s), "l"(g));
    else
        asm volatile("cp.async.cg.shared.global [%0], [%1], 16, 0;" :: "r"(s), "l"(g));
}

// ---------------- fp32 -> bf16 bulk convert (vectorized) --------------------
__global__ void f2bf_k(const float4* __restrict__ s, __nv_bfloat162* __restrict__ d, int n4) {
    int i = blockIdx.x * blockDim.x + threadIdx.x;
    for (; i < n4; i += gridDim.x * blockDim.x) {
        float4 v = s[i];
        d[2*i]   = __floats2bfloat162_rn(v.x, v.y);
        d[2*i+1] = __floats2bfloat162_rn(v.z, v.w);
    }
}

// ---------------- RMSNorm (reads xin, writes bf16 h) -------------------------
__global__ void rmsnorm_k(const float* __restrict__ xin, const float* __restrict__ w) {
    int row = blockIdx.x;
    const float* xr = xin + (size_t)row * DM;
    __shared__ float red[256];
    float s = 0.f;
    for (int i = threadIdx.x; i < DM; i += 256) { float v = xr[i]; s += v * v; }
    red[threadIdx.x] = s;
    __syncthreads();
    for (int off = 128; off > 0; off >>= 1) {
        if (threadIdx.x < off) red[threadIdx.x] += red[threadIdx.x + off];
        __syncthreads();
    }
    float inv = rsqrtf(red[0] * (1.f / DM) + 1e-5f);
    bf16* hr = g_h_bf + (size_t)row * DM;
    for (int i = threadIdx.x; i < DM; i += 256)
        hr[i] = __float2bfloat16(xr[i] * inv * w[i]);
}

// ---------------- bf16 tensor-core NT GEMM ----------------------------------
// 3-stage cp.async pipeline, refill-before-compute, 2 CTAs/SM (regs<=128).
// C[m,n] = sum_k A[m,k]*B[n,k] (+epilogue). A,B bf16; C fp32.
// Block tile 128x128x64, 8 warps (warp 64x32), mma.m16n8k16 bf16.
#define STAGEB 32768u
#define NSTAGE 3
#define GSMEM  (NSTAGE * STAGEB)

__global__ __launch_bounds__(256, 2) void bf16gemm_nt_k(
    const bf16* __restrict__ A, int lda,
    const bf16* __restrict__ B, int ldb,
    float* __restrict__ C, int ldc,
    const float* __restrict__ bias,
    const float* __restrict__ resid,
    int M, int N, int K, int epi,
    int kspan, size_t cspan)
{
    extern __shared__ char smem[];
    A += (size_t)blockIdx.z * kspan;
    B += (size_t)blockIdx.z * kspan;
    C += (size_t)blockIdx.z * cspan;

    const int tid  = threadIdx.x;
    const int warp = tid >> 5;
    const int lane = tid & 31;
    const int m0 = blockIdx.y * 128;
    const int n0 = blockIdx.x * 128;
    const int wm = (warp >> 2) * 64;
    const int wn = (warp & 3) * 32;

    float c[4][4][4];
#pragma unroll
    for (int i = 0; i < 4; i++)
#pragma unroll
        for (int j = 0; j < 4; j++)
#pragma unroll
            for (int r = 0; r < 4; r++) c[i][j][r] = 0.f;

    const uint32_t sbase = (uint32_t)__cvta_generic_to_shared(smem);
    const int nk = K >> 6;

    const int lane8 = lane & 7;
    const int lmat  = lane >> 3;
    const int cpr = tid >> 1;            // row 0..127
    const int cpc = (tid & 1) << 2;      // chunk base 0 or 4

    // ---- prologue: issue stages 0..NSTAGE-2 (uniform group count) ----
#pragma unroll
    for (int t = 0; t < NSTAGE - 1; t++) {
        if (t < nk) {
            uint32_t st = sbase + (uint32_t)t * STAGEB;
            const int k0 = t << 6;
#pragma unroll
            for (int i = 0; i < 4; i++) {
                int cc = cpc + i;
                uint32_t so = (uint32_t)((cpr << 7) + ((cc ^ (cpr & 7)) << 4));
                cp16(st + so,           A + (size_t)(m0 + cpr) * lda + k0 + cc * 8, (m0 + cpr) < M);
                cp16(st + 16384u + so,  B + (size_t)(n0 + cpr) * ldb + k0 + cc * 8, (n0 + cpr) < N);
            }
        }
        asm volatile("cp.async.commit_group;" ::: "memory");
    }

    for (int kt = 0; kt < nk; kt++) {
        asm volatile("cp.async.wait_group %0;" :: "n"(NSTAGE - 2) : "memory");
        __syncthreads();

        // refill stage (kt+NSTAGE-1)%NSTAGE before compute
        if (kt + NSTAGE - 1 < nk) {
            const int k0 = (kt + NSTAGE - 1) << 6;
            uint32_t st = sbase + (uint32_t)((kt + NSTAGE - 1) % NSTAGE) * STAGEB;
#pragma unroll
            for (int i = 0; i < 4; i++) {
                int cc = cpc + i;
                uint32_t so = (uint32_t)((cpr << 7) + ((cc ^ (cpr & 7)) << 4));
                cp16(st + so,          A + (size_t)(m0 + cpr) * lda + k0 + cc * 8, (m0 + cpr) < M);
                cp16(st + 16384u + so, B + (size_t)(n0 + cpr) * ldb + k0 + cc * 8, (n0 + cpr) < N);
            }
        }
        asm volatile("cp.async.commit_group;" ::: "memory");

        // ---- compute on stage kt%NSTAGE (single-buffered fragments) ----
        const uint32_t sA = sbase + (uint32_t)(kt % NSTAGE) * STAGEB;
        const uint32_t sB = sA + 16384u;

#pragma unroll
        for (int ks = 0; ks < 4; ks++) {
            uint32_t a[4][4];
#pragma unroll
            for (int mt = 0; mt < 4; mt++) {
                int ar = wm + mt * 16 + ((lmat & 1) << 3) + lane8;
                int ac = (ks << 1) + (lmat >> 1);
                uint32_t addr = sA + (uint32_t)((ar << 7) + ((ac ^ (ar & 7)) << 4));
                asm volatile("ldmatrix.sync.aligned.m8n8.x4.shared.b16 {%0,%1,%2,%3}, [%4];"
                             : "=r"(a[mt][0]), "=r"(a[mt][1]),
                               "=r"(a[mt][2]), "=r"(a[mt][3]) : "r"(addr));
            }
            uint32_t b[4][2];
#pragma unroll
            for (int np = 0; np < 2; np++) {
                int br = wn + np * 16 + ((lmat >> 1) << 3) + lane8;
                int bc = (ks << 1) + (lmat & 1);
                uint32_t addr = sB + (uint32_t)((br << 7) + ((bc ^ (br & 7)) << 4));
                asm volatile("ldmatrix.sync.aligned.m8n8.x4.shared.b16 {%0,%1,%2,%3}, [%4];"
                             : "=r"(b[np*2][0]), "=r"(b[np*2][1]),
                               "=r"(b[np*2+1][0]), "=r"(b[np*2+1][1]) : "r"(addr));
            }
#pragma unroll
            for (int mt = 0; mt < 4; mt++)
#pragma unroll
                for (int nt = 0; nt < 4; nt++) {
                    asm volatile(
                        "mma.sync.aligned.m16n8k16.row.col.f32.bf16.bf16.f32 "
                        "{%0,%1,%2,%3}, {%4,%5,%6,%7}, {%8,%9}, {%0,%1,%2,%3};"
                        : "+f"(c[mt][nt][0]), "+f"(c[mt][nt][1]),
                          "+f"(c[mt][nt][2]), "+f"(c[mt][nt][3])
                        : "r"(a[mt][0]), "r"(a[mt][1]), "r"(a[mt][2]), "r"(a[mt][3]),
                          "r"(b[nt][0]), "r"(b[nt][1]));
                }
        }
    }

    // ---- epilogue (float2 stores) ----
#pragma unroll
    for (int mt = 0; mt < 4; mt++) {
#pragma unroll
        for (int nt = 0; nt < 4; nt++) {
            int m = m0 + wm + mt * 16 + (lane >> 2);
            int n = n0 + wn + nt * 8 + 2 * (lane & 3);
#pragma unroll
            for (int half = 0; half < 2; half++) {
                int mm = m + half * 8;
                if (mm >= M || n >= N) continue;
                float v0 = c[mt][nt][half * 2];
                float v1 = c[mt][nt][half * 2 + 1];
                if (epi == 1) {
                    v0 = softplusf(v0 + bias[n]);
                    v1 = softplusf(v1 + bias[n + 1]);
                } else if (epi == 2) {
                    const float2 rv = *(const float2*)(resid + (size_t)mm * ldc + n);
                    v0 += rv.x; v1 += rv.y;
                }
                *(float2*)(C + (size_t)mm * ldc + n) = make_float2(v0, v1);
            }
        }
    }
}

// ---------------- split-K reduction (fp32 + bf16 out) ------------------------
__global__ void reduce_part_k() {
    int i = blockIdx.x * blockDim.x + threadIdx.x;
    if (i >= MROWS * DBC_W) return;
    float s = 0.f;
#pragma unroll
    for (int p = 0; p < KSPLIT; p++) s += g_part[(size_t)p * MROWS * DBC_W + i];
    g_dbc[i] = s;
    g_dbc_bf[i] = __float2bfloat16(s);
}

// ---------------- causal depthwise conv1d (k=4) + SiLU ----------------------
__global__ void conv_silu_k(const float* __restrict__ cw, const float* __restrict__ cb) {
    int idx = blockIdx.x * blockDim.x + threadIdx.x;
    if (idx >= MROWS * DI) return;
    int d = idx % DI;
    int l = (idx / DI) % LSEQ;
    int b = idx / (DI * LSEQ);
    float acc = cb[d];
#pragma unroll
    for (int k = 0; k < 4; k++) {
        int ls = l - 3 + k;
        if (ls >= 0)
            acc = fmaf(g_xz[((size_t)(b * LSEQ + ls)) * (2 * DI) + d], cw[d * 4 + k], acc);
    }
    float v = siluf(acc);
    g_xc[idx] = v;
    g_xc_bf[idx] = __float2bfloat16(v);
}

// ---------------- selective scan (pipelined), writes bf16 u -----------------
__global__ void scan_k(const float* __restrict__ A_log, const float* __restrict__ Dw) {
    int t = blockIdx.x * blockDim.x + threadIdx.x;
    int n = t & 15;
    int p = t >> 4;
    if (p >= BATCH * DI) return;
    int d = p % DI;
    int b = p / DI;

    float A  = -__expf(A_log[d * NST + n]);
    float Dd = Dw[d];
    float h  = 0.f;

    size_t rowD  = (size_t)(b * LSEQ) * DI + d;
    size_t row96 = (size_t)(b * LSEQ) * DBC_W;
    size_t rowZ  = (size_t)(b * LSEQ) * (2 * DI) + DI + d;

    float dt = g_delta[rowD];
    float xv = g_xc[rowD];
    float Bn = g_dbc[row96 + RK + n];
    float Cn = g_dbc[row96 + RK + NST + n];
    float zv = g_xz[rowZ];

#pragma unroll 2
    for (int l = 0; l < LSEQ; l++) {
        size_t rowD1  = rowD + DI;
        size_t row961 = row96 + DBC_W;
        size_t rowZ1  = rowZ + 2 * DI;
        float dt1 = 0.f, xv1 = 0.f, Bn1 = 0.f, Cn1 = 0.f, zv1 = 0.f;
        if (l + 1 < LSEQ) {
            dt1 = g_delta[rowD1];
            xv1 = g_xc[rowD1];
            Bn1 = g_dbc[row961 + RK + n];
            Cn1 = g_dbc[row961 + RK + NST + n];
            zv1 = g_xz[rowZ1];
        }

        h = fmaf(__expf(dt * A), h, dt * xv * Bn);

        float y = h * Cn;
        y += __shfl_xor_sync(0xffffffffu, y, 8);
        y += __shfl_xor_sync(0xffffffffu, y, 4);
        y += __shfl_xor_sync(0xffffffffu, y, 2);
        y += __shfl_xor_sync(0xffffffffu, y, 1);

        if (n == 0)
            g_u_bf[rowD] = __float2bfloat16((y + Dd * xv) * siluf(zv));

        dt = dt1; xv = xv1; Bn = Bn1; Cn = Cn1; zv = zv1;
        rowD = rowD1; row96 = row961; rowZ = rowZ1;
    }
}

// ---------------- host orchestration ----------------------------------------
extern "C" void kernel_launch(void* const* d_in, const int* in_sizes, int n_in,
                              void* d_out, int out_size) {
    const float* x      = (const float*)d_in[0];
    const float* norm_w = (const float*)d_in[1];
    const float* W_in   = (const float*)d_in[2];
    const float* conv_w = (const float*)d_in[3];
    const float* conv_b = (const float*)d_in[4];
    const float* W_x    = (const float*)d_in[5];
    const float* W_dt   = (const float*)d_in[6];
    const float* b_dt   = (const float*)d_in[7];
    const float* A_log  = (const float*)d_in[8];
    const float* Dpar   = (const float*)d_in[9];
    const float* W_out  = (const float*)d_in[10];
    float* out = (float*)d_out;

    float *px, *pxz, *ppart, *pdelta;
    bf16 *ph_bf, *pxc_bf, *pdbc_bf, *pu_bf, *pWin, *pWx, *pWdt, *pWout;
    cudaGetSymbolAddress((void**)&px,     g_x);
    cudaGetSymbolAddress((void**)&pxz,    g_xz);
    cudaGetSymbolAddress((void**)&ppart,  g_part);
    cudaGetSymbolAddress((void**)&pdelta, g_delta);
    cudaGetSymbolAddress((void**)&ph_bf,  g_h_bf);
    cudaGetSymbolAddress((void**)&pxc_bf, g_xc_bf);
    cudaGetSymbolAddress((void**)&pdbc_bf,g_dbc_bf);
    cudaGetSymbolAddress((void**)&pu_bf,  g_u_bf);
    cudaGetSymbolAddress((void**)&pWin,   g_Win_bf);
    cudaGetSymbolAddress((void**)&pWx,    g_Wx_bf);
    cudaGetSymbolAddress((void**)&pWdt,   g_Wdt_bf);
    cudaGetSymbolAddress((void**)&pWout,  g_Wout_bf);

    const int M = MROWS;
    cudaFuncSetAttribute(bf16gemm_nt_k,
                         cudaFuncAttributeMaxDynamicSharedMemorySize, GSMEM);

    dim3 thr(256);

    // weights -> bf16 (launches 0-3)
    f2bf_k<<<1184, 256>>>((const float4*)W_in,  (__nv_bfloat162*)pWin,  NL * 2 * DI * DM / 4);
    f2bf_k<<<296,  256>>>((const float4*)W_x,   (__nv_bfloat162*)pWx,   NL * DBC_W * DI / 4);
    f2bf_k<<<296,  256>>>((const float4*)W_dt,  (__nv_bfloat162*)pWdt,  NL * DI * RK / 4);
    f2bf_k<<<1184, 256>>>((const float4*)W_out, (__nv_bfloat162*)pWout, NL * DM * DI / 4);

    for (int l = 0; l < NL; l++) {
        const float* xres = (l == 0) ? x : px;   // residual stream source

        // launch 4: rmsnorm; launch 5: gemm1 (ncu -s 5 captures this)
        rmsnorm_k<<<M, 256>>>(xres, norm_w + (size_t)l * DM);

        // 2) xz = h @ W_in^T   [M, 2*DI]
        {
            dim3 g(2 * DI / 128, M / 128, 1);
            bf16gemm_nt_k<<<g, thr, GSMEM>>>(ph_bf, DM, pWin + (size_t)l * 2 * DI * DM, DM,
                                             pxz, 2 * DI, nullptr, nullptr,
                                             M, 2 * DI, DM, 0, 0, 0);
        }

        conv_silu_k<<<(MROWS*DI + 255) / 256, 256>>>(
            conv_w + (size_t)l * DI * 4, conv_b + (size_t)l * DI);

        // 4) dbc = xc @ W_x^T   [M, 96]  split-K=8 + reduce
        {
            const int Kc = DI / KSPLIT;  // 256
            dim3 g(1, M / 128, KSPLIT);
            bf16gemm_nt_k<<<g, thr, GSMEM>>>(pxc_bf, DI, pWx + (size_t)l * DBC_W * DI, DI,
                                             ppart, DBC_W, nullptr, nullptr,
                                             M, DBC_W, Kc, 0,
                                             Kc, (size_t)M * DBC_W);
            reduce_part_k<<<(MROWS * DBC_W + 255) / 256, 256>>>();
        }

        // 5) delta = softplus(dbc[:, :64] @ W_dt^T + b_dt)   [M, DI]
        {
            dim3 g(DI / 128, M / 128, 1);
            bf16gemm_nt_k<<<g, thr, GSMEM>>>(pdbc_bf, DBC_W, pWdt + (size_t)l * DI * RK, RK,
                                             pdelta, DI, b_dt + (size_t)l * DI, nullptr,
                                             M, DI, RK, 1, 0, 0);
        }

        scan_k<<<(BATCH * DI * NST) / 256, 256>>>(
            A_log + (size_t)l * DI * NST, Dpar + (size_t)l * DI);

        // 7) x_next = xres + u @ W_out^T   [M, DM]
        {
            float* Cout = (l == NL - 1) ? out : px;
            dim3 g(DM / 128, M / 128, 1);
            bf16gemm_nt_k<<<g, thr, GSMEM>>>(pu_bf, DI, pWout + (size_t)l * DM * DI, DI,
                                             Cout, DM, nullptr, xres,
                                             M, DM, DI, 2, 0, 0);
        }
    }
}